// round 15
// baseline (speedup 1.0000x reference)
#include <cuda_runtime.h>
#include <cuda_bf16.h>
#include <cstdint>
#include <cstddef>

// ----------------------------------------------------------------------------
// Decoder step: Bahdanau attention + GRU cell + fc, B=128, S=1024, U=1024.
// R15 = R12 score kernel (best measured config: 16 warps/SM, warp 32x32,
// 3-stage, 2 CTAs/SM) + 2-s-tile persistent CTAs (half the waves, continuous
// pipeline across the s-tile boundary) + int8 context. Tail = R11 split-K.
// ----------------------------------------------------------------------------

#define BATCH   128
#define SEQ     1024
#define UNITS   1024
#define INDIM   64
#define GINLEN  (UNITS + INDIM)   // 1088
#define G3U     (3 * UNITS)       // 3072
#define NT2     16                // 1024 / 64 n-tiles

#define TOT1    (BATCH * UNITS)   // 131072
#define TOT3    (BATCH * G3U)     // 393216
#define TOTFC   (BATCH * INDIM)   // 8192

// ---------------- scratch (no allocations allowed) ----------------
__device__ __align__(16) int8_t g_enc_q1[(size_t)BATCH * SEQ * UNITS];
__device__ __align__(16) int8_t g_enc_q0[(size_t)BATCH * SEQ * UNITS];
__device__ __align__(16) int8_t g_w1t_q1[(size_t)UNITS * UNITS];        // W1^T
__device__ __align__(16) int8_t g_w1t_q0[(size_t)UNITS * UNITS];
__device__ __align__(16) float  g_sA    [BATCH * SEQ];
__device__ __align__(16) float  g_sB    [UNITS];
__device__ __align__(16) float  g_sBinv [UNITS];
__device__ __align__(16) float  g_q     [TOT1];
__device__ __align__(16) float  g_part  [NT2 * BATCH * SEQ];
__device__ __align__(16) float  g_gin   [BATCH * GINLEN];
__device__ __align__(16) float  g_z     [TOT1];
__device__ __align__(16) float  g_rh    [TOT1];
__device__ __align__(16) float  g_state [TOT1];
// split-K partial buffers
__device__ __align__(16) float  g_pq    [8  * TOT1];
__device__ __align__(16) float  g_pxg   [4  * TOT3];
__device__ __align__(16) float  g_phwr  [4  * TOT3];
__device__ __align__(16) float  g_prhwr [8  * TOT1];
__device__ __align__(16) float  g_pfc   [16 * TOTFC];

// ======================= PTX helpers =======================
__device__ __forceinline__ uint32_t smem_u32(const void* p) {
    uint32_t a;
    asm("{ .reg .u64 t; cvta.to.shared.u64 t, %1; cvt.u32.u64 %0, t; }" : "=r"(a) : "l"(p));
    return a;
}
#define CP_ASYNC16(dst, src) \
    asm volatile("cp.async.cg.shared.global [%0], [%1], 16;" :: "r"(dst), "l"(src))
#define CP_COMMIT() asm volatile("cp.async.commit_group;" ::: "memory")

__device__ __forceinline__ void ldsm_x4(uint32_t r[4], uint32_t addr) {
    asm volatile("ldmatrix.sync.aligned.m8n8.x4.shared.b16 {%0,%1,%2,%3}, [%4];"
                 : "=r"(r[0]), "=r"(r[1]), "=r"(r[2]), "=r"(r[3]) : "r"(addr));
}
// s8 x s8 -> s32, m16n8k32
__device__ __forceinline__ void mma_s8(int c[4], const uint32_t a[4],
                                       uint32_t b0, uint32_t b1) {
    asm volatile(
        "mma.sync.aligned.m16n8k32.row.col.s32.s8.s8.s32 "
        "{%0,%1,%2,%3}, {%4,%5,%6,%7}, {%8,%9}, {%0,%1,%2,%3};"
        : "+r"(c[0]), "+r"(c[1]), "+r"(c[2]), "+r"(c[3])
        : "r"(a[0]), "r"(a[1]), "r"(a[2]), "r"(a[3]), "r"(b0), "r"(b1));
}

// ======================= quantization kernels =======================
__global__ __launch_bounds__(256)
void quant_enc_kernel(const float* __restrict__ enc)
{
    const int warp = threadIdx.x >> 5, lane = threadIdx.x & 31;
    const size_t row = (size_t)blockIdx.x * 8 + warp;
    const float4* p4 = reinterpret_cast<const float4*>(enc + row * UNITS);

    float4 v[8];
    float mx = 0.f;
    #pragma unroll
    for (int i = 0; i < 8; i++) {
        v[i] = p4[lane + 32 * i];
        mx = fmaxf(mx, fmaxf(fmaxf(fabsf(v[i].x), fabsf(v[i].y)),
                             fmaxf(fabsf(v[i].z), fabsf(v[i].w))));
    }
    #pragma unroll
    for (int s = 16; s > 0; s >>= 1)
        mx = fmaxf(mx, __shfl_xor_sync(0xFFFFFFFF, mx, s));

    const float sinv = mx > 0.f ? 127.f / mx : 0.f;
    if (lane == 0) g_sA[row] = mx > 0.f ? mx / 127.f : 0.f;

    char4* q1 = reinterpret_cast<char4*>(g_enc_q1 + row * UNITS);
    char4* q0 = reinterpret_cast<char4*>(g_enc_q0 + row * UNITS);
    #pragma unroll
    for (int i = 0; i < 8; i++) {
        float a[4] = {v[i].x * sinv, v[i].y * sinv, v[i].z * sinv, v[i].w * sinv};
        char h[4], l[4];
        #pragma unroll
        for (int j = 0; j < 4; j++) {
            int hi = __float2int_rn(a[j]);
            int lo = __float2int_rn((a[j] - (float)hi) * 128.f);
            h[j] = (char)hi; l[j] = (char)lo;
        }
        q1[lane + 32 * i] = make_char4(h[0], h[1], h[2], h[3]);
        q0[lane + 32 * i] = make_char4(l[0], l[1], l[2], l[3]);
    }
}

__global__ __launch_bounds__(256)
void w1_colmax_kernel(const float* __restrict__ W1)
{
    __shared__ float smax[8][32];
    const int n0 = blockIdx.x * 32;
    const int nn = threadIdx.x & 31, kg = threadIdx.x >> 5;
    float mx = 0.f;
    for (int k = kg; k < UNITS; k += 8)
        mx = fmaxf(mx, fabsf(W1[(size_t)k * UNITS + n0 + nn]));
    smax[kg][nn] = mx;
    __syncthreads();
    if (threadIdx.x < 32) {
        float m = smax[0][nn];
        #pragma unroll
        for (int i = 1; i < 8; i++) m = fmaxf(m, smax[i][nn]);
        g_sB[n0 + nn]    = m > 0.f ? m / 127.f : 0.f;
        g_sBinv[n0 + nn] = m > 0.f ? 127.f / m : 0.f;
    }
}

__global__ __launch_bounds__(256)
void quant_w1_kernel(const float* __restrict__ W1)
{
    __shared__ float tile[32][33];
    const int n0 = blockIdx.x * 32, k0 = blockIdx.y * 32;
    const int tx = threadIdx.x, ty = threadIdx.y;
    #pragma unroll
    for (int i = 0; i < 4; i++)
        tile[ty + i * 8][tx] = W1[(size_t)(k0 + ty + i * 8) * UNITS + n0 + tx];
    __syncthreads();
    #pragma unroll
    for (int i = 0; i < 4; i++) {
        const int n = n0 + ty + i * 8;
        float v = tile[tx][ty + i * 8] * g_sBinv[n];
        int hi = __float2int_rn(v);
        int lo = __float2int_rn((v - (float)hi) * 128.f);
        size_t o = (size_t)n * UNITS + k0 + tx;
        g_w1t_q1[o] = (int8_t)hi;
        g_w1t_q0[o] = (int8_t)lo;
    }
}

// ======================= int8 warp-MMA score GEMM =======================
// CTA: (b, s-SUPER-tile 256, n-tile 64), 256 threads, warp grid 4(m)x2(n),
// warp tile 32x32. Each CTA processes TWO 128-row s-tiles back-to-back with
// a continuous cp.async pipeline (32 global chunks). Stage = 24KB, 3 stages
// = 72KB -> 2 CTAs/SM; __launch_bounds__(256,2) caps regs at 128.
#define T_A1    0
#define T_A0    8192
#define T_B1    16384
#define T_B0    20480
#define STAGE_B 24576
#define NSTAGE  3
#define NCHUNK  16
#define NGC     32                        // 2 s-tiles x 16 chunks
#define SCORE_SMEM (NSTAGE * STAGE_B)     // 73728

__device__ __forceinline__ void fill_stage(uint32_t stage,
                                           const char* a1, const char* a0,
                                           const char* b1, const char* b0,
                                           int chunk, int tid)
{
    const int kb = chunk * 64;
    // A: 128 rows x 4 16B-chunks = 512 slots / 256 threads
    #pragma unroll
    for (int t = 0; t < 2; t++) {
        const int idx = t * 256 + tid;
        const int row = idx >> 2, c = idx & 3;
        const uint32_t so = (uint32_t)(row * 64 + ((c ^ ((row >> 1) & 3)) << 4));
        const size_t   go = (size_t)row * UNITS + kb + c * 16;
        CP_ASYNC16(stage + T_A1 + so, a1 + go);
        CP_ASYNC16(stage + T_A0 + so, a0 + go);
    }
    // B: 64 rows x 4 chunks = 256 slots
    {
        const int row = tid >> 2, c = tid & 3;
        const uint32_t so = (uint32_t)(row * 64 + ((c ^ ((row >> 1) & 3)) << 4));
        const size_t   go = (size_t)row * UNITS + kb + c * 16;
        CP_ASYNC16(stage + T_B1 + so, b1 + go);
        CP_ASYNC16(stage + T_B0 + so, b0 + go);
    }
}

__device__ __forceinline__ void score_epilogue(
    int acc1[2][4][4], int accm[2][4][4], float* sacc,
    const float* __restrict__ q, const float* __restrict__ b1v,
    const float* __restrict__ V, const float* sArow,
    int b, int s0, int n0, int nt, int warp_m, int warp_n, int lane, int tid)
{
    const size_t qb = (size_t)b * UNITS;
    #pragma unroll
    for (int mi = 0; mi < 2; mi++) {
        float p0 = 0.f, p1 = 0.f;
        const int r   = warp_m * 32 + mi * 16 + (lane >> 2);
        const float sa0 = sArow[r], sa1 = sArow[r + 8];
        #pragma unroll
        for (int ni = 0; ni < 4; ni++) {
            #pragma unroll
            for (int cc = 0; cc < 4; cc++) {
                int n = n0 + warp_n * 32 + ni * 8 + (lane & 3) * 2 + (cc & 1);
                float sa  = (cc < 2) ? sa0 : sa1;
                float val = sa * g_sB[n] *
                            ((float)acc1[mi][ni][cc] + (float)accm[mi][ni][cc] * 0.0078125f);
                float t = V[n] * tanhf(val + q[qb + n] + b1v[n]);
                if (cc < 2) p0 += t; else p1 += t;
            }
        }
        p0 += __shfl_xor_sync(0xFFFFFFFF, p0, 1);
        p0 += __shfl_xor_sync(0xFFFFFFFF, p0, 2);
        p1 += __shfl_xor_sync(0xFFFFFFFF, p1, 1);
        p1 += __shfl_xor_sync(0xFFFFFFFF, p1, 2);
        if ((lane & 3) == 0) {
            atomicAdd(&sacc[r],     p0);
            atomicAdd(&sacc[r + 8], p1);
        }
    }
    __syncthreads();
    if (tid < 128)
        g_part[(size_t)nt * (BATCH * SEQ) + (size_t)b * SEQ + s0 + tid] = sacc[tid];
}

__global__ __launch_bounds__(256, 2)
void score_mma_kernel(const float* __restrict__ q,
                      const float* __restrict__ b1v,
                      const float* __restrict__ V)
{
    extern __shared__ __align__(128) char smem[];
    __shared__ float sacc[128];
    const uint32_t sb = smem_u32(smem);

    const int tid    = threadIdx.x;
    const int lane   = tid & 31;
    const int wid    = tid >> 5;
    const int warp_m = wid & 3;           // 0..3  (32 rows each)
    const int warp_n = wid >> 2;          // 0..1  (32 cols each)
    const int nt     = blockIdx.x;
    const int n0     = nt * 64;
    const int sbase  = blockIdx.y * 256;  // s-super-tile (two 128-row halves)
    const int b      = blockIdx.z;

    if (tid < 128) sacc[tid] = 0.f;

    // per-half A pointers; B shared by both halves
    const char* a1h[2] = {
        (const char*)(g_enc_q1 + ((size_t)b * SEQ + sbase) * UNITS),
        (const char*)(g_enc_q1 + ((size_t)b * SEQ + sbase + 128) * UNITS) };
    const char* a0h[2] = {
        (const char*)(g_enc_q0 + ((size_t)b * SEQ + sbase) * UNITS),
        (const char*)(g_enc_q0 + ((size_t)b * SEQ + sbase + 128) * UNITS) };
    const char* b1p = (const char*)(g_w1t_q1 + (size_t)n0 * UNITS);
    const char* b0p = (const char*)(g_w1t_q0 + (size_t)n0 * UNITS);

    fill_stage(sb,           a1h[0], a0h[0], b1p, b0p, 0, tid); CP_COMMIT();
    fill_stage(sb + STAGE_B, a1h[0], a0h[0], b1p, b0p, 1, tid); CP_COMMIT();

    int acc1[2][4][4], accm[2][4][4];
    #pragma unroll
    for (int mi = 0; mi < 2; mi++)
        #pragma unroll
        for (int ni = 0; ni < 4; ni++)
            #pragma unroll
            for (int c = 0; c < 4; c++) { acc1[mi][ni][c] = 0; accm[mi][ni][c] = 0; }

    uint32_t a_off[2], xa[2], b_off[2], xb[2];
    #pragma unroll
    for (int mi = 0; mi < 2; mi++) {
        int row = warp_m * 32 + mi * 16 + (lane & 7) + ((lane >> 3) & 1) * 8;
        a_off[mi] = (uint32_t)row * 64;
        xa[mi]    = (uint32_t)((row >> 1) & 3);
    }
    #pragma unroll
    for (int p = 0; p < 2; p++) {
        int row = warp_n * 32 + p * 16 + (lane & 7) + ((lane >> 3) & 1) * 8;
        b_off[p] = (uint32_t)row * 64;
        xb[p]    = (uint32_t)((row >> 1) & 3);
    }
    const uint32_t ch = (uint32_t)(lane >> 4);   // k16-half selector

    #pragma unroll 1
    for (int gc = 0; gc < NGC; gc++) {
        if (gc >= NGC - 1) asm volatile("cp.async.wait_group 0;" ::: "memory");
        else               asm volatile("cp.async.wait_group 1;" ::: "memory");
        __syncthreads();   // chunk gc visible; iteration gc-1 MMAs done

        const uint32_t slot = sb + (uint32_t)(gc % NSTAGE) * STAGE_B;

        if (gc + 2 < NGC) {   // slot (gc+2)%3 was consumed at iter gc-1
            const int gf = gc + 2;
            const int hf = gf >> 4;
            fill_stage(sb + (uint32_t)(gf % NSTAGE) * STAGE_B,
                       a1h[hf], a0h[hf], b1p, b0p, gf & 15, tid);
            CP_COMMIT();
        }

        #pragma unroll
        for (int j = 0; j < 2; j++) {     // two k32 steps per 64-chunk
            const uint32_t cj = (uint32_t)(j * 2) + ch;
            uint32_t bf1[2][4], bf0[2][4];
            #pragma unroll
            for (int p = 0; p < 2; p++) {
                uint32_t ad = slot + T_B1 + b_off[p] + ((cj ^ xb[p]) << 4);
                ldsm_x4(bf1[p], ad);
                ldsm_x4(bf0[p], ad + (T_B0 - T_B1));
            }
            #pragma unroll
            for (int mi = 0; mi < 2; mi++) {
                uint32_t ad = slot + T_A1 + a_off[mi] + ((cj ^ xa[mi]) << 4);
                uint32_t af1[4], af0[4];
                ldsm_x4(af1, ad);
                ldsm_x4(af0, ad + (T_A0 - T_A1));
                #pragma unroll
                for (int ni = 0; ni < 4; ni++) {
                    const int p = ni >> 1, h = ni & 1;
                    mma_s8(acc1[mi][ni], af1, bf1[p][h], bf1[p][h + 2]);
                    mma_s8(accm[mi][ni], af1, bf0[p][h], bf0[p][h + 2]);
                    mma_s8(accm[mi][ni], af0, bf1[p][h], bf1[p][h + 2]);
                }
            }
        }

        if (gc == NCHUNK - 1) {
            // epilogue for s-tile half 0; pipeline (fills for 16,17) continues
            score_epilogue(acc1, accm, sacc, q, b1v, V,
                           g_sA + (size_t)b * SEQ + sbase,
                           b, sbase, n0, nt, warp_m, warp_n, lane, tid);
            __syncthreads();
            if (tid < 128) sacc[tid] = 0.f;
            #pragma unroll
            for (int mi = 0; mi < 2; mi++)
                #pragma unroll
                for (int ni = 0; ni < 4; ni++)
                    #pragma unroll
                    for (int c2 = 0; c2 < 4; c2++) {
                        acc1[mi][ni][c2] = 0; accm[mi][ni][c2] = 0;
                    }
        }
    }

    // epilogue for s-tile half 1
    score_epilogue(acc1, accm, sacc, q, b1v, V,
                   g_sA + (size_t)b * SEQ + sbase + 128,
                   b, sbase + 128, n0, nt, warp_m, warp_n, lane, tid);
}

// ======================= fp32 split-K SGEMM (R11, unchanged) =============
__device__ __forceinline__
void sgemm_part_body(const float* __restrict__ A, int lda,
                     const float* __restrict__ B, int ldb,
                     float* __restrict__ Cpart, int ldc,
                     int kbeg, int kend, int n0)
{
    __shared__ float As[16][128 + 4];
    __shared__ float Bs[16][64];

    const int tid = threadIdx.x;
    const int tm  = (tid >> 4) * 8;
    const int tn  = (tid & 15) * 4;

    float acc[8][4];
    #pragma unroll
    for (int i = 0; i < 8; i++)
        #pragma unroll
        for (int j = 0; j < 4; j++) acc[i][j] = 0.f;

    for (int kk = kbeg; kk < kend; kk += 16) {
        #pragma unroll
        for (int it = 0; it < 2; it++) {
            int t4 = it * 256 + tid;
            int row = t4 >> 2, col = (t4 & 3) * 4;
            float4 v = *reinterpret_cast<const float4*>(&A[(size_t)row * lda + kk + col]);
            As[col + 0][row] = v.x; As[col + 1][row] = v.y;
            As[col + 2][row] = v.z; As[col + 3][row] = v.w;
        }
        {
            int row = tid >> 4, c4 = (tid & 15) * 4;
            *reinterpret_cast<float4*>(&Bs[row][c4]) =
                *reinterpret_cast<const float4*>(&B[(size_t)(kk + row) * ldb + n0 + c4]);
        }
        __syncthreads();
        #pragma unroll
        for (int k = 0; k < 16; k++) {
            float ra[8], rb[4];
            *reinterpret_cast<float4*>(&ra[0]) = *reinterpret_cast<const float4*>(&As[k][tm]);
            *reinterpret_cast<float4*>(&ra[4]) = *reinterpret_cast<const float4*>(&As[k][tm + 4]);
            *reinterpret_cast<float4*>(&rb[0]) = *reinterpret_cast<const float4*>(&Bs[k][tn]);
            #pragma unroll
            for (int i = 0; i < 8; i++)
                #pragma unroll
                for (int j = 0; j < 4; j++)
                    acc[i][j] += ra[i] * rb[j];
        }
        __syncthreads();
    }
    #pragma unroll
    for (int j = 0; j < 4; j++)
        #pragma unroll
        for (int i = 0; i < 8; i++)
            Cpart[(size_t)(tm + i) * ldc + n0 + tn + j] = acc[i][j];
}

__global__ __launch_bounds__(256)
void sgemm_split_kernel(const float* __restrict__ A, int lda,
                        const float* __restrict__ B, int ldb,
                        float* __restrict__ part, int ldc,
                        int K, int S)
{
    const int s = blockIdx.y;
    const int steps = K / 16;
    const int per   = steps / S;
    sgemm_part_body(A, lda, B, ldb, part + (size_t)s * 128 * ldc, ldc,
                    s * per * 16, (s + 1) * per * 16, blockIdx.x * 64);
}

__global__ __launch_bounds__(256)
void sgemm_dual_split_kernel(const float* __restrict__ gin,
                             const float* __restrict__ hidden,
                             const float* __restrict__ Wk,
                             const float* __restrict__ Wr,
                             int S)
{
    const int s = blockIdx.y;
    if (blockIdx.z == 0) {
        const int steps = GINLEN / 16;
        const int per   = steps / S;
        sgemm_part_body(gin, GINLEN, Wk, G3U, g_pxg + (size_t)s * TOT3, G3U,
                        s * per * 16, (s + 1) * per * 16, blockIdx.x * 64);
    } else {
        const int steps = UNITS / 16;
        const int per   = steps / S;
        sgemm_part_body(hidden, UNITS, Wr, G3U, g_phwr + (size_t)s * TOT3, G3U,
                        s * per * 16, (s + 1) * per * 16, blockIdx.x * 64);
    }
}

__global__ __launch_bounds__(256)
void reduce_q_kernel(const float* __restrict__ b2)
{
    int i = blockIdx.x * 256 + threadIdx.x;
    float s = 0.f;
    #pragma unroll
    for (int t = 0; t < 8; t++) s += g_pq[(size_t)t * TOT1 + i];
    g_q[i] = s + b2[i & 1023];
}

__global__ __launch_bounds__(256)
void reduce_fc_kernel(const float* __restrict__ bfc, float* __restrict__ out_fc)
{
    int i = blockIdx.x * 256 + threadIdx.x;
    float s = 0.f;
    #pragma unroll
    for (int t = 0; t < 16; t++) s += g_pfc[(size_t)t * TOTFC + i];
    out_fc[i] = s + bfc[i & 63];
}

// ======================= remaining pipeline =======================
__global__ __launch_bounds__(256)
void softmax_kernel(const float* __restrict__ bV, float* __restrict__ out_attn)
{
    __shared__ float sh[SEQ];
    __shared__ float red[256];
    const int b = blockIdx.x, tid = threadIdx.x;
    const float bv = bV[0];

    float m = -1e30f;
    for (int i = tid; i < SEQ; i += 256) {
        size_t o = (size_t)b * SEQ + i;
        float s = bv;
        #pragma unroll
        for (int t = 0; t < NT2; t++)
            s += g_part[(size_t)t * (BATCH * SEQ) + o];
        sh[i] = s;
        m = fmaxf(m, s);
    }
    red[tid] = m; __syncthreads();
    for (int s = 128; s > 0; s >>= 1) {
        if (tid < s) red[tid] = fmaxf(red[tid], red[tid + s]);
        __syncthreads();
    }
    m = red[0]; __syncthreads();

    float sum = 0.f;
    for (int i = tid; i < SEQ; i += 256) {
        float e = expf(sh[i] - m);
        sh[i] = e;
        sum += e;
    }
    red[tid] = sum; __syncthreads();
    for (int s = 128; s > 0; s >>= 1) {
        if (tid < s) red[tid] += red[tid + s];
        __syncthreads();
    }
    float inv = 1.f / red[0];
    for (int i = tid; i < SEQ; i += 256)
        out_attn[(size_t)b * SEQ + i] = sh[i] * inv;
}

// context from int8 enc copy: ctx[b,u] = sum_s attn*sA * (q1 + q0/128)
__global__ __launch_bounds__(256)
void context_kernel(const float* __restrict__ attn)
{
    __shared__ float w[SEQ];
    const int b = blockIdx.y, u0 = blockIdx.x * 256, tid = threadIdx.x;

    for (int i = tid; i < SEQ; i += 256)
        w[i] = attn[(size_t)b * SEQ + i] * g_sA[(size_t)b * SEQ + i];
    __syncthreads();

    const int8_t* e1 = g_enc_q1 + (size_t)b * SEQ * UNITS + u0 + tid;
    const int8_t* e0 = g_enc_q0 + (size_t)b * SEQ * UNITS + u0 + tid;
    float acc = 0.f;
    #pragma unroll 8
    for (int s = 0; s < SEQ; s++) {
        float v = (float)e1[(size_t)s * UNITS] +
                  (float)e0[(size_t)s * UNITS] * 0.0078125f;
        acc += w[s] * v;
    }
    g_gin[(size_t)b * GINLEN + u0 + tid] = acc;
}

__global__ void copyx_kernel(const float* __restrict__ x)
{
    int i = blockIdx.x * 256 + threadIdx.x;
    if (i < BATCH * INDIM) {
        int b = i >> 6, u = i & 63;
        g_gin[(size_t)b * GINLEN + UNITS + u] = x[i];
    }
}

__global__ __launch_bounds__(256)
void gates_kernel(const float* __restrict__ hidden, const float* __restrict__ bg)
{
    int i = blockIdx.x * 256 + threadIdx.x;
    int b = i >> 10, u = i & 1023;
    size_t oz = (size_t)b * G3U + u;
    size_t orr = oz + UNITS;
    float xz = bg[u], xr = bg[UNITS + u];
    #pragma unroll
    for (int t = 0; t < 4; t++) {
        xz += g_pxg[(size_t)t * TOT3 + oz] + g_phwr[(size_t)t * TOT3 + oz];
        xr += g_pxg[(size_t)t * TOT3 + orr] + g_phwr[(size_t)t * TOT3 + orr];
    }
    float z = 1.f / (1.f + expf(-xz));
    float r = 1.f / (1.f + expf(-xr));
    g_z[i]  = z;
    g_rh[i] = r * hidden[i];
}

__global__ __launch_bounds__(256)
void state_kernel(const float* __restrict__ hidden, const float* __restrict__ bg,
                  float* __restrict__ out_state)
{
    int i = blockIdx.x * 256 + threadIdx.x;
    int b = i >> 10, u = i & 1023;
    size_t oh = (size_t)b * G3U + 2 * UNITS + u;
    float xh = bg[2 * UNITS + u];
    #pragma unroll
    for (int t = 0; t < 4; t++) xh += g_pxg[(size_t)t * TOT3 + oh];
    float rw = 0.f;
    #pragma unroll
    for (int t = 0; t < 8; t++) rw += g_prhwr[(size_t)t * TOT1 + i];
    float hh = tanhf(xh + rw);
    float z  = g_z[i];
    float st = z * hidden[i] + (1.f - z) * hh;
    out_state[i] = st;
    g_state[i]   = st;
}

// ----------------------------------------------------------------------------
extern "C" void kernel_launch(void* const* d_in, const int* in_sizes, int n_in,
                              void* d_out_v, int out_size)
{
    const float* x      = (const float*)d_in[0];
    const float* hidden = (const float*)d_in[1];
    const float* enc    = (const float*)d_in[2];
    const float* W1     = (const float*)d_in[3];
    const float* b1     = (const float*)d_in[4];
    const float* W2     = (const float*)d_in[5];
    const float* b2     = (const float*)d_in[6];
    const float* V      = (const float*)d_in[7];
    const float* bV     = (const float*)d_in[8];
    const float* Wk     = (const float*)d_in[9];
    const float* Wr     = (const float*)d_in[10];
    const float* bg     = (const float*)d_in[11];
    const float* Wfc    = (const float*)d_in[12];
    const float* bfc    = (const float*)d_in[13];

    float* d_out     = (float*)d_out_v;
    float* out_fc    = d_out;
    float* out_state = d_out + BATCH * INDIM;
    float* out_attn  = d_out + BATCH * INDIM + BATCH * UNITS;

    float *q, *rh, *state, *pq, *prhwr, *pfc, *gin;
    cudaGetSymbolAddress((void**)&q,     g_q);
    cudaGetSymbolAddress((void**)&rh,    g_rh);
    cudaGetSymbolAddress((void**)&state, g_state);
    cudaGetSymbolAddress((void**)&pq,    g_pq);
    cudaGetSymbolAddress((void**)&prhwr, g_prhwr);
    cudaGetSymbolAddress((void**)&pfc,   g_pfc);
    cudaGetSymbolAddress((void**)&gin,   g_gin);

    cudaFuncSetAttribute(score_mma_kernel,
                         cudaFuncAttributeMaxDynamicSharedMemorySize, SCORE_SMEM);

    // 1. quantize operands
    quant_enc_kernel<<<(BATCH * SEQ) / 8, 256>>>(enc);
    w1_colmax_kernel<<<UNITS / 32, 256>>>(W1);
    quant_w1_kernel<<<dim3(32, 32), dim3(32, 8)>>>(W1);
    // 2. q = hidden @ W2 + b2 (split-K 8)
    sgemm_split_kernel<<<dim3(UNITS / 64, 8), 256>>>(hidden, UNITS, W2, UNITS, pq, UNITS, UNITS, 8);
    reduce_q_kernel<<<TOT1 / 256, 256>>>(b2);
    // 3. int8 tensor-core score GEMM (2-s-tile persistent CTAs, half the waves)
    score_mma_kernel<<<dim3(NT2, SEQ / 256, BATCH), 256, SCORE_SMEM>>>(q, b1, V);
    // 4. fused reduce + softmax (output slab 3)
    softmax_kernel<<<BATCH, 256>>>(bV, out_attn);
    // 5. gin = [context | x] (context from int8 enc)
    copyx_kernel<<<(BATCH * INDIM + 255) / 256, 256>>>(x);
    context_kernel<<<dim3(UNITS / 256, BATCH), 256>>>(out_attn);
    // 6. GRU projections split-K
    sgemm_dual_split_kernel<<<dim3(G3U / 64, 4, 2), 256>>>(gin, hidden, Wk, Wr, 4);
    // 7. gates (fused partial reduction)
    gates_kernel<<<TOT1 / 256, 256>>>(hidden, bg);
    // 8. (r*h) @ Wr_h split-K 8
    sgemm_split_kernel<<<dim3(UNITS / 64, 8), 256>>>(rh, UNITS, Wr + 2 * UNITS, G3U, prhwr, UNITS, UNITS, 8);
    // 9. state (fused partial reduction, output slab 2)
    state_kernel<<<TOT1 / 256, 256>>>(hidden, bg, out_state);
    // 10. out = state @ Wfc + bfc (split-K 16)
    sgemm_split_kernel<<<dim3(INDIM / 64, 16), 256>>>(state, UNITS, Wfc, INDIM, pfc, INDIM, UNITS, 16);
    reduce_fc_kernel<<<TOTFC / 256, 256>>>(bfc, out_fc);
}

// round 16
// speedup vs baseline: 1.0263x; 1.0263x over previous
#include <cuda_runtime.h>
#include <cuda_bf16.h>
#include <cstdint>
#include <cstddef>

// ----------------------------------------------------------------------------
// Decoder step: Bahdanau attention + GRU cell + fc, B=128, S=1024, U=1024.
// R16 = R12 compute path verbatim (measured best: int8 score GEMM, 16 warps/SM,
// warp 32x32, 3-stage, 2 CTAs/SM; fp32 context; split-K tail) + graph-parallel
// streams: quant_enc || w1-quant || q-chain, and hidden@Wr under the score.
// ----------------------------------------------------------------------------

#define BATCH   128
#define SEQ     1024
#define UNITS   1024
#define INDIM   64
#define GINLEN  (UNITS + INDIM)   // 1088
#define G3U     (3 * UNITS)       // 3072
#define NT2     16                // 1024 / 64 n-tiles

#define TOT1    (BATCH * UNITS)   // 131072
#define TOT3    (BATCH * G3U)     // 393216
#define TOTFC   (BATCH * INDIM)   // 8192

// ---------------- scratch (no allocations allowed) ----------------
__device__ __align__(16) int8_t g_enc_q1[(size_t)BATCH * SEQ * UNITS];
__device__ __align__(16) int8_t g_enc_q0[(size_t)BATCH * SEQ * UNITS];
__device__ __align__(16) int8_t g_w1t_q1[(size_t)UNITS * UNITS];        // W1^T
__device__ __align__(16) int8_t g_w1t_q0[(size_t)UNITS * UNITS];
__device__ __align__(16) float  g_sA    [BATCH * SEQ];
__device__ __align__(16) float  g_sB    [UNITS];
__device__ __align__(16) float  g_sBinv [UNITS];
__device__ __align__(16) float  g_q     [TOT1];
__device__ __align__(16) float  g_part  [NT2 * BATCH * SEQ];
__device__ __align__(16) float  g_gin   [BATCH * GINLEN];
__device__ __align__(16) float  g_z     [TOT1];
__device__ __align__(16) float  g_rh    [TOT1];
__device__ __align__(16) float  g_state [TOT1];
// split-K partial buffers
__device__ __align__(16) float  g_pq    [8  * TOT1];
__device__ __align__(16) float  g_pxg   [4  * TOT3];
__device__ __align__(16) float  g_phwr  [4  * TOT3];
__device__ __align__(16) float  g_prhwr [8  * TOT1];
__device__ __align__(16) float  g_pfc   [16 * TOTFC];

// ======================= PTX helpers =======================
__device__ __forceinline__ uint32_t smem_u32(const void* p) {
    uint32_t a;
    asm("{ .reg .u64 t; cvta.to.shared.u64 t, %1; cvt.u32.u64 %0, t; }" : "=r"(a) : "l"(p));
    return a;
}
#define CP_ASYNC16(dst, src) \
    asm volatile("cp.async.cg.shared.global [%0], [%1], 16;" :: "r"(dst), "l"(src))
#define CP_COMMIT() asm volatile("cp.async.commit_group;" ::: "memory")

__device__ __forceinline__ void ldsm_x4(uint32_t r[4], uint32_t addr) {
    asm volatile("ldmatrix.sync.aligned.m8n8.x4.shared.b16 {%0,%1,%2,%3}, [%4];"
                 : "=r"(r[0]), "=r"(r[1]), "=r"(r[2]), "=r"(r[3]) : "r"(addr));
}
// s8 x s8 -> s32, m16n8k32
__device__ __forceinline__ void mma_s8(int c[4], const uint32_t a[4],
                                       uint32_t b0, uint32_t b1) {
    asm volatile(
        "mma.sync.aligned.m16n8k32.row.col.s32.s8.s8.s32 "
        "{%0,%1,%2,%3}, {%4,%5,%6,%7}, {%8,%9}, {%0,%1,%2,%3};"
        : "+r"(c[0]), "+r"(c[1]), "+r"(c[2]), "+r"(c[3])
        : "r"(a[0]), "r"(a[1]), "r"(a[2]), "r"(a[3]), "r"(b0), "r"(b1));
}

// ======================= quantization kernels =======================
__global__ __launch_bounds__(256)
void quant_enc_kernel(const float* __restrict__ enc)
{
    const int warp = threadIdx.x >> 5, lane = threadIdx.x & 31;
    const size_t row = (size_t)blockIdx.x * 8 + warp;
    const float4* p4 = reinterpret_cast<const float4*>(enc + row * UNITS);

    float4 v[8];
    float mx = 0.f;
    #pragma unroll
    for (int i = 0; i < 8; i++) {
        v[i] = p4[lane + 32 * i];
        mx = fmaxf(mx, fmaxf(fmaxf(fabsf(v[i].x), fabsf(v[i].y)),
                             fmaxf(fabsf(v[i].z), fabsf(v[i].w))));
    }
    #pragma unroll
    for (int s = 16; s > 0; s >>= 1)
        mx = fmaxf(mx, __shfl_xor_sync(0xFFFFFFFF, mx, s));

    const float sinv = mx > 0.f ? 127.f / mx : 0.f;
    if (lane == 0) g_sA[row] = mx > 0.f ? mx / 127.f : 0.f;

    char4* q1 = reinterpret_cast<char4*>(g_enc_q1 + row * UNITS);
    char4* q0 = reinterpret_cast<char4*>(g_enc_q0 + row * UNITS);
    #pragma unroll
    for (int i = 0; i < 8; i++) {
        float a[4] = {v[i].x * sinv, v[i].y * sinv, v[i].z * sinv, v[i].w * sinv};
        char h[4], l[4];
        #pragma unroll
        for (int j = 0; j < 4; j++) {
            int hi = __float2int_rn(a[j]);
            int lo = __float2int_rn((a[j] - (float)hi) * 128.f);
            h[j] = (char)hi; l[j] = (char)lo;
        }
        q1[lane + 32 * i] = make_char4(h[0], h[1], h[2], h[3]);
        q0[lane + 32 * i] = make_char4(l[0], l[1], l[2], l[3]);
    }
}

__global__ __launch_bounds__(256)
void w1_colmax_kernel(const float* __restrict__ W1)
{
    __shared__ float smax[8][32];
    const int n0 = blockIdx.x * 32;
    const int nn = threadIdx.x & 31, kg = threadIdx.x >> 5;
    float mx = 0.f;
    for (int k = kg; k < UNITS; k += 8)
        mx = fmaxf(mx, fabsf(W1[(size_t)k * UNITS + n0 + nn]));
    smax[kg][nn] = mx;
    __syncthreads();
    if (threadIdx.x < 32) {
        float m = smax[0][nn];
        #pragma unroll
        for (int i = 1; i < 8; i++) m = fmaxf(m, smax[i][nn]);
        g_sB[n0 + nn]    = m > 0.f ? m / 127.f : 0.f;
        g_sBinv[n0 + nn] = m > 0.f ? 127.f / m : 0.f;
    }
}

__global__ __launch_bounds__(256)
void quant_w1_kernel(const float* __restrict__ W1)
{
    __shared__ float tile[32][33];
    const int n0 = blockIdx.x * 32, k0 = blockIdx.y * 32;
    const int tx = threadIdx.x, ty = threadIdx.y;
    #pragma unroll
    for (int i = 0; i < 4; i++)
        tile[ty + i * 8][tx] = W1[(size_t)(k0 + ty + i * 8) * UNITS + n0 + tx];
    __syncthreads();
    #pragma unroll
    for (int i = 0; i < 4; i++) {
        const int n = n0 + ty + i * 8;
        float v = tile[tx][ty + i * 8] * g_sBinv[n];
        int hi = __float2int_rn(v);
        int lo = __float2int_rn((v - (float)hi) * 128.f);
        size_t o = (size_t)n * UNITS + k0 + tx;
        g_w1t_q1[o] = (int8_t)hi;
        g_w1t_q0[o] = (int8_t)lo;
    }
}

// ======================= int8 warp-MMA score GEMM (R12 verbatim) ==========
#define T_A1    0
#define T_A0    8192
#define T_B1    16384
#define T_B0    20480
#define STAGE_B 24576
#define NSTAGE  3
#define NCHUNK  16
#define SCORE_SMEM (NSTAGE * STAGE_B)     // 73728

__device__ __forceinline__ void fill_stage(uint32_t stage,
                                           const char* a1, const char* a0,
                                           const char* b1, const char* b0,
                                           int chunk, int tid)
{
    const int kb = chunk * 64;
    #pragma unroll
    for (int t = 0; t < 2; t++) {
        const int idx = t * 256 + tid;
        const int row = idx >> 2, c = idx & 3;
        const uint32_t so = (uint32_t)(row * 64 + ((c ^ ((row >> 1) & 3)) << 4));
        const size_t   go = (size_t)row * UNITS + kb + c * 16;
        CP_ASYNC16(stage + T_A1 + so, a1 + go);
        CP_ASYNC16(stage + T_A0 + so, a0 + go);
    }
    {
        const int row = tid >> 2, c = tid & 3;
        const uint32_t so = (uint32_t)(row * 64 + ((c ^ ((row >> 1) & 3)) << 4));
        const size_t   go = (size_t)row * UNITS + kb + c * 16;
        CP_ASYNC16(stage + T_B1 + so, b1 + go);
        CP_ASYNC16(stage + T_B0 + so, b0 + go);
    }
}

__global__ __launch_bounds__(256, 2)
void score_mma_kernel(const float* __restrict__ q,
                      const float* __restrict__ b1v,
                      const float* __restrict__ V)
{
    extern __shared__ __align__(128) char smem[];
    __shared__ float sacc[128];
    const uint32_t sb = smem_u32(smem);

    const int tid    = threadIdx.x;
    const int lane   = tid & 31;
    const int wid    = tid >> 5;
    const int warp_m = wid & 3;
    const int warp_n = wid >> 2;
    const int n0     = blockIdx.x * 64;
    const int s0     = blockIdx.y * 128;
    const int b      = blockIdx.z;

    if (tid < 128) sacc[tid] = 0.f;

    const char* a1p = (const char*)(g_enc_q1 + ((size_t)b * SEQ + s0) * UNITS);
    const char* a0p = (const char*)(g_enc_q0 + ((size_t)b * SEQ + s0) * UNITS);
    const char* b1p = (const char*)(g_w1t_q1 + (size_t)n0 * UNITS);
    const char* b0p = (const char*)(g_w1t_q0 + (size_t)n0 * UNITS);

    fill_stage(sb,           a1p, a0p, b1p, b0p, 0, tid); CP_COMMIT();
    fill_stage(sb + STAGE_B, a1p, a0p, b1p, b0p, 1, tid); CP_COMMIT();

    int acc1[2][4][4], accm[2][4][4];
    #pragma unroll
    for (int mi = 0; mi < 2; mi++)
        #pragma unroll
        for (int ni = 0; ni < 4; ni++)
            #pragma unroll
            for (int c = 0; c < 4; c++) { acc1[mi][ni][c] = 0; accm[mi][ni][c] = 0; }

    uint32_t a_off[2], xa[2], b_off[2], xb[2];
    #pragma unroll
    for (int mi = 0; mi < 2; mi++) {
        int row = warp_m * 32 + mi * 16 + (lane & 7) + ((lane >> 3) & 1) * 8;
        a_off[mi] = (uint32_t)row * 64;
        xa[mi]    = (uint32_t)((row >> 1) & 3);
    }
    #pragma unroll
    for (int p = 0; p < 2; p++) {
        int row = warp_n * 32 + p * 16 + (lane & 7) + ((lane >> 3) & 1) * 8;
        b_off[p] = (uint32_t)row * 64;
        xb[p]    = (uint32_t)((row >> 1) & 3);
    }
    const uint32_t ch = (uint32_t)(lane >> 4);

    #pragma unroll 1
    for (int c = 0; c < NCHUNK; c++) {
        if (c >= NCHUNK - 1) asm volatile("cp.async.wait_group 0;" ::: "memory");
        else                 asm volatile("cp.async.wait_group 1;" ::: "memory");
        __syncthreads();

        const uint32_t slot = sb + (uint32_t)(c % NSTAGE) * STAGE_B;

        if (c + 2 < NCHUNK) {
            fill_stage(sb + (uint32_t)((c + 2) % NSTAGE) * STAGE_B,
                       a1p, a0p, b1p, b0p, c + 2, tid);
            CP_COMMIT();
        }

        #pragma unroll
        for (int j = 0; j < 2; j++) {
            const uint32_t cj = (uint32_t)(j * 2) + ch;
            uint32_t bf1[2][4], bf0[2][4];
            #pragma unroll
            for (int p = 0; p < 2; p++) {
                uint32_t ad = slot + T_B1 + b_off[p] + ((cj ^ xb[p]) << 4);
                ldsm_x4(bf1[p], ad);
                ldsm_x4(bf0[p], ad + (T_B0 - T_B1));
            }
            #pragma unroll
            for (int mi = 0; mi < 2; mi++) {
                uint32_t ad = slot + T_A1 + a_off[mi] + ((cj ^ xa[mi]) << 4);
                uint32_t af1[4], af0[4];
                ldsm_x4(af1, ad);
                ldsm_x4(af0, ad + (T_A0 - T_A1));
                #pragma unroll
                for (int ni = 0; ni < 4; ni++) {
                    const int p = ni >> 1, h = ni & 1;
                    mma_s8(acc1[mi][ni], af1, bf1[p][h], bf1[p][h + 2]);
                    mma_s8(accm[mi][ni], af1, bf0[p][h], bf0[p][h + 2]);
                    mma_s8(accm[mi][ni], af0, bf1[p][h], bf1[p][h + 2]);
                }
            }
        }
    }

    const size_t qb = (size_t)b * UNITS;
    const float* sArow = g_sA + (size_t)b * SEQ + s0;
    #pragma unroll
    for (int mi = 0; mi < 2; mi++) {
        float p0 = 0.f, p1 = 0.f;
        const int r   = warp_m * 32 + mi * 16 + (lane >> 2);
        const float sa0 = sArow[r], sa1 = sArow[r + 8];
        #pragma unroll
        for (int ni = 0; ni < 4; ni++) {
            #pragma unroll
            for (int cc = 0; cc < 4; cc++) {
                int n = n0 + warp_n * 32 + ni * 8 + (lane & 3) * 2 + (cc & 1);
                float sa  = (cc < 2) ? sa0 : sa1;
                float val = sa * g_sB[n] *
                            ((float)acc1[mi][ni][cc] + (float)accm[mi][ni][cc] * 0.0078125f);
                float t = V[n] * tanhf(val + q[qb + n] + b1v[n]);
                if (cc < 2) p0 += t; else p1 += t;
            }
        }
        p0 += __shfl_xor_sync(0xFFFFFFFF, p0, 1);
        p0 += __shfl_xor_sync(0xFFFFFFFF, p0, 2);
        p1 += __shfl_xor_sync(0xFFFFFFFF, p1, 1);
        p1 += __shfl_xor_sync(0xFFFFFFFF, p1, 2);
        if ((lane & 3) == 0) {
            atomicAdd(&sacc[r],     p0);
            atomicAdd(&sacc[r + 8], p1);
        }
    }
    __syncthreads();
    if (tid < 128)
        g_part[(size_t)blockIdx.x * (BATCH * SEQ) + (size_t)b * SEQ + s0 + tid] = sacc[tid];
}

// ======================= fp32 split-K SGEMM (R11, unchanged) =============
__device__ __forceinline__
void sgemm_part_body(const float* __restrict__ A, int lda,
                     const float* __restrict__ B, int ldb,
                     float* __restrict__ Cpart, int ldc,
                     int kbeg, int kend, int n0)
{
    __shared__ float As[16][128 + 4];
    __shared__ float Bs[16][64];

    const int tid = threadIdx.x;
    const int tm  = (tid >> 4) * 8;
    const int tn  = (tid & 15) * 4;

    float acc[8][4];
    #pragma unroll
    for (int i = 0; i < 8; i++)
        #pragma unroll
        for (int j = 0; j < 4; j++) acc[i][j] = 0.f;

    for (int kk = kbeg; kk < kend; kk += 16) {
        #pragma unroll
        for (int it = 0; it < 2; it++) {
            int t4 = it * 256 + tid;
            int row = t4 >> 2, col = (t4 & 3) * 4;
            float4 v = *reinterpret_cast<const float4*>(&A[(size_t)row * lda + kk + col]);
            As[col + 0][row] = v.x; As[col + 1][row] = v.y;
            As[col + 2][row] = v.z; As[col + 3][row] = v.w;
        }
        {
            int row = tid >> 4, c4 = (tid & 15) * 4;
            *reinterpret_cast<float4*>(&Bs[row][c4]) =
                *reinterpret_cast<const float4*>(&B[(size_t)(kk + row) * ldb + n0 + c4]);
        }
        __syncthreads();
        #pragma unroll
        for (int k = 0; k < 16; k++) {
            float ra[8], rb[4];
            *reinterpret_cast<float4*>(&ra[0]) = *reinterpret_cast<const float4*>(&As[k][tm]);
            *reinterpret_cast<float4*>(&ra[4]) = *reinterpret_cast<const float4*>(&As[k][tm + 4]);
            *reinterpret_cast<float4*>(&rb[0]) = *reinterpret_cast<const float4*>(&Bs[k][tn]);
            #pragma unroll
            for (int i = 0; i < 8; i++)
                #pragma unroll
                for (int j = 0; j < 4; j++)
                    acc[i][j] += ra[i] * rb[j];
        }
        __syncthreads();
    }
    #pragma unroll
    for (int j = 0; j < 4; j++)
        #pragma unroll
        for (int i = 0; i < 8; i++)
            Cpart[(size_t)(tm + i) * ldc + n0 + tn + j] = acc[i][j];
}

__global__ __launch_bounds__(256)
void sgemm_split_kernel(const float* __restrict__ A, int lda,
                        const float* __restrict__ B, int ldb,
                        float* __restrict__ part, int ldc,
                        int K, int S)
{
    const int s = blockIdx.y;
    const int steps = K / 16;
    const int per   = steps / S;
    sgemm_part_body(A, lda, B, ldb, part + (size_t)s * 128 * ldc, ldc,
                    s * per * 16, (s + 1) * per * 16, blockIdx.x * 64);
}

__global__ __launch_bounds__(256)
void reduce_q_kernel(const float* __restrict__ b2)
{
    int i = blockIdx.x * 256 + threadIdx.x;
    float s = 0.f;
    #pragma unroll
    for (int t = 0; t < 8; t++) s += g_pq[(size_t)t * TOT1 + i];
    g_q[i] = s + b2[i & 1023];
}

__global__ __launch_bounds__(256)
void reduce_fc_kernel(const float* __restrict__ bfc, float* __restrict__ out_fc)
{
    int i = blockIdx.x * 256 + threadIdx.x;
    float s = 0.f;
    #pragma unroll
    for (int t = 0; t < 16; t++) s += g_pfc[(size_t)t * TOTFC + i];
    out_fc[i] = s + bfc[i & 63];
}

// ======================= remaining pipeline =======================
__global__ __launch_bounds__(256)
void softmax_kernel(const float* __restrict__ bV, float* __restrict__ out_attn)
{
    __shared__ float sh[SEQ];
    __shared__ float red[256];
    const int b = blockIdx.x, tid = threadIdx.x;
    const float bv = bV[0];

    float m = -1e30f;
    for (int i = tid; i < SEQ; i += 256) {
        size_t o = (size_t)b * SEQ + i;
        float s = bv;
        #pragma unroll
        for (int t = 0; t < NT2; t++)
            s += g_part[(size_t)t * (BATCH * SEQ) + o];
        sh[i] = s;
        m = fmaxf(m, s);
    }
    red[tid] = m; __syncthreads();
    for (int s = 128; s > 0; s >>= 1) {
        if (tid < s) red[tid] = fmaxf(red[tid], red[tid + s]);
        __syncthreads();
    }
    m = red[0]; __syncthreads();

    float sum = 0.f;
    for (int i = tid; i < SEQ; i += 256) {
        float e = expf(sh[i] - m);
        sh[i] = e;
        sum += e;
    }
    red[tid] = sum; __syncthreads();
    for (int s = 128; s > 0; s >>= 1) {
        if (tid < s) red[tid] += red[tid + s];
        __syncthreads();
    }
    float inv = 1.f / red[0];
    for (int i = tid; i < SEQ; i += 256)
        out_attn[(size_t)b * SEQ + i] = sh[i] * inv;
}

__global__ __launch_bounds__(256)
void context_kernel(const float* __restrict__ enc, const float* __restrict__ attn)
{
    __shared__ float w[SEQ];
    const int b = blockIdx.y, u0 = blockIdx.x * 256, tid = threadIdx.x;

    for (int i = tid; i < SEQ; i += 256)
        w[i] = attn[(size_t)b * SEQ + i];
    __syncthreads();

    const float* e = enc + (size_t)b * SEQ * UNITS + u0 + tid;
    float acc = 0.f;
    #pragma unroll 8
    for (int s = 0; s < SEQ; s++)
        acc += w[s] * e[(size_t)s * UNITS];
    g_gin[(size_t)b * GINLEN + u0 + tid] = acc;
}

__global__ void copyx_kernel(const float* __restrict__ x)
{
    int i = blockIdx.x * 256 + threadIdx.x;
    if (i < BATCH * INDIM) {
        int b = i >> 6, u = i & 63;
        g_gin[(size_t)b * GINLEN + UNITS + u] = x[i];
    }
}

__global__ __launch_bounds__(256)
void gates_kernel(const float* __restrict__ hidden, const float* __restrict__ bg)
{
    int i = blockIdx.x * 256 + threadIdx.x;
    int b = i >> 10, u = i & 1023;
    size_t oz = (size_t)b * G3U + u;
    size_t orr = oz + UNITS;
    float xz = bg[u], xr = bg[UNITS + u];
    #pragma unroll
    for (int t = 0; t < 4; t++) {
        xz += g_pxg[(size_t)t * TOT3 + oz] + g_phwr[(size_t)t * TOT3 + oz];
        xr += g_pxg[(size_t)t * TOT3 + orr] + g_phwr[(size_t)t * TOT3 + orr];
    }
    float z = 1.f / (1.f + expf(-xz));
    float r = 1.f / (1.f + expf(-xr));
    g_z[i]  = z;
    g_rh[i] = r * hidden[i];
}

__global__ __launch_bounds__(256)
void state_kernel(const float* __restrict__ hidden, const float* __restrict__ bg,
                  float* __restrict__ out_state)
{
    int i = blockIdx.x * 256 + threadIdx.x;
    int b = i >> 10, u = i & 1023;
    size_t oh = (size_t)b * G3U + 2 * UNITS + u;
    float xh = bg[2 * UNITS + u];
    #pragma unroll
    for (int t = 0; t < 4; t++) xh += g_pxg[(size_t)t * TOT3 + oh];
    float rw = 0.f;
    #pragma unroll
    for (int t = 0; t < 8; t++) rw += g_prhwr[(size_t)t * TOT1 + i];
    float hh = tanhf(xh + rw);
    float z  = g_z[i];
    float st = z * hidden[i] + (1.f - z) * hh;
    out_state[i] = st;
    g_state[i]   = st;
}

// ----------------------------------------------------------------------------
extern "C" void kernel_launch(void* const* d_in, const int* in_sizes, int n_in,
                              void* d_out_v, int out_size)
{
    const float* x      = (const float*)d_in[0];
    const float* hidden = (const float*)d_in[1];
    const float* enc    = (const float*)d_in[2];
    const float* W1     = (const float*)d_in[3];
    const float* b1     = (const float*)d_in[4];
    const float* W2     = (const float*)d_in[5];
    const float* b2     = (const float*)d_in[6];
    const float* V      = (const float*)d_in[7];
    const float* bV     = (const float*)d_in[8];
    const float* Wk     = (const float*)d_in[9];
    const float* Wr     = (const float*)d_in[10];
    const float* bg     = (const float*)d_in[11];
    const float* Wfc    = (const float*)d_in[12];
    const float* bfc    = (const float*)d_in[13];

    float* d_out     = (float*)d_out_v;
    float* out_fc    = d_out;
    float* out_state = d_out + BATCH * INDIM;
    float* out_attn  = d_out + BATCH * INDIM + BATCH * UNITS;

    float *q, *rh, *state, *pq, *pxg, *phwr, *prhwr, *pfc, *gin;
    cudaGetSymbolAddress((void**)&q,     g_q);
    cudaGetSymbolAddress((void**)&rh,    g_rh);
    cudaGetSymbolAddress((void**)&state, g_state);
    cudaGetSymbolAddress((void**)&pq,    g_pq);
    cudaGetSymbolAddress((void**)&pxg,   g_pxg);
    cudaGetSymbolAddress((void**)&phwr,  g_phwr);
    cudaGetSymbolAddress((void**)&prhwr, g_prhwr);
    cudaGetSymbolAddress((void**)&pfc,   g_pfc);
    cudaGetSymbolAddress((void**)&gin,   g_gin);

    // one-time: streams (non-blocking), events, smem attr
    static cudaStream_t s1 = nullptr, s2 = nullptr, s3 = nullptr;
    static cudaEvent_t evRoot, ev1, ev2, ev3;
    if (!s1) {
        cudaStreamCreateWithFlags(&s1, cudaStreamNonBlocking);
        cudaStreamCreateWithFlags(&s2, cudaStreamNonBlocking);
        cudaStreamCreateWithFlags(&s3, cudaStreamNonBlocking);
        cudaEventCreateWithFlags(&evRoot, cudaEventDisableTiming);
        cudaEventCreateWithFlags(&ev1,    cudaEventDisableTiming);
        cudaEventCreateWithFlags(&ev2,    cudaEventDisableTiming);
        cudaEventCreateWithFlags(&ev3,    cudaEventDisableTiming);
        cudaFuncSetAttribute(score_mma_kernel,
                             cudaFuncAttributeMaxDynamicSharedMemorySize, SCORE_SMEM);
    }

    // ---- fork: bring s1/s2/s3 into the capture graph ----
    cudaEventRecord(evRoot, 0);
    cudaStreamWaitEvent(s1, evRoot, 0);
    cudaStreamWaitEvent(s2, evRoot, 0);
    cudaStreamWaitEvent(s3, evRoot, 0);

    // main stream: the big DRAM-bound enc quantization
    quant_enc_kernel<<<(BATCH * SEQ) / 8, 256>>>(enc);
    // s1: W1 quantization chain
    w1_colmax_kernel<<<UNITS / 32, 256, 0, s1>>>(W1);
    quant_w1_kernel<<<dim3(32, 32), dim3(32, 8), 0, s1>>>(W1);
    // s2: q = hidden @ W2 + b2
    sgemm_split_kernel<<<dim3(UNITS / 64, 8), 256, 0, s2>>>(hidden, UNITS, W2, UNITS, pq, UNITS, UNITS, 8);
    reduce_q_kernel<<<TOT1 / 256, 256, 0, s2>>>(b2);
    // s3: hidden @ Wr partials (independent until gates; overlaps the score)
    sgemm_split_kernel<<<dim3(G3U / 64, 4), 256, 0, s3>>>(hidden, UNITS, Wr, G3U, phwr, G3U, UNITS, 4);

    // join s1/s2 before the score GEMM
    cudaEventRecord(ev1, s1);
    cudaEventRecord(ev2, s2);
    cudaStreamWaitEvent(0, ev1, 0);
    cudaStreamWaitEvent(0, ev2, 0);

    // int8 tensor-core score GEMM (R12 config)
    score_mma_kernel<<<dim3(NT2, SEQ / 128, BATCH), 256, SCORE_SMEM>>>(q, b1, V);
    // fused reduce + softmax (output slab 3)
    softmax_kernel<<<BATCH, 256>>>(bV, out_attn);
    // gin = [context | x] (fp32 enc, as in R12)
    copyx_kernel<<<(BATCH * INDIM + 255) / 256, 256>>>(x);
    context_kernel<<<dim3(UNITS / 256, BATCH), 256>>>(enc, out_attn);
    // gin @ Wk partials
    sgemm_split_kernel<<<dim3(G3U / 64, 4), 256>>>(gin, GINLEN, Wk, G3U, pxg, G3U, GINLEN, 4);

    // join s3 (hwr) before gates
    cudaEventRecord(ev3, s3);
    cudaStreamWaitEvent(0, ev3, 0);

    gates_kernel<<<TOT1 / 256, 256>>>(hidden, bg);
    sgemm_split_kernel<<<dim3(UNITS / 64, 8), 256>>>(rh, UNITS, Wr + 2 * UNITS, G3U, prhwr, UNITS, UNITS, 8);
    state_kernel<<<TOT1 / 256, 256>>>(hidden, bg, out_state);
    sgemm_split_kernel<<<dim3(INDIM / 64, 16), 256>>>(state, UNITS, Wfc, INDIM, pfc, INDIM, UNITS, 16);
    reduce_fc_kernel<<<TOTFC / 256, 256>>>(bfc, out_fc);
}

// round 17
// speedup vs baseline: 1.0281x; 1.0017x over previous
#include <cuda_runtime.h>
#include <cuda_bf16.h>
#include <cstdint>
#include <cstddef>

// ----------------------------------------------------------------------------
// Decoder step: Bahdanau attention + GRU cell + fc, B=128, S=1024, U=1024.
// R17 = R12 verbatim + ONE change: accm MMA RAW chain de-serialized at the
// proven 16-warp/SM config (R13 tested this split only at 8 warps - confound).
// Pass 1 per mi: acc1+=A1B1, accm+=A1B0 (8 independent MMAs); pass 2: the 4
// dependent accm+=A0B1, now >=4 issues away from their RAW producers.
// ----------------------------------------------------------------------------

#define BATCH   128
#define SEQ     1024
#define UNITS   1024
#define INDIM   64
#define GINLEN  (UNITS + INDIM)   // 1088
#define G3U     (3 * UNITS)       // 3072
#define NT2     16                // 1024 / 64 n-tiles

#define TOT1    (BATCH * UNITS)   // 131072
#define TOT3    (BATCH * G3U)     // 393216
#define TOTFC   (BATCH * INDIM)   // 8192

// ---------------- scratch (no allocations allowed) ----------------
__device__ __align__(16) int8_t g_enc_q1[(size_t)BATCH * SEQ * UNITS];
__device__ __align__(16) int8_t g_enc_q0[(size_t)BATCH * SEQ * UNITS];
__device__ __align__(16) int8_t g_w1t_q1[(size_t)UNITS * UNITS];        // W1^T
__device__ __align__(16) int8_t g_w1t_q0[(size_t)UNITS * UNITS];
__device__ __align__(16) float  g_sA    [BATCH * SEQ];
__device__ __align__(16) float  g_sB    [UNITS];
__device__ __align__(16) float  g_sBinv [UNITS];
__device__ __align__(16) float  g_q     [TOT1];
__device__ __align__(16) float  g_part  [NT2 * BATCH * SEQ];
__device__ __align__(16) float  g_gin   [BATCH * GINLEN];
__device__ __align__(16) float  g_z     [TOT1];
__device__ __align__(16) float  g_rh    [TOT1];
__device__ __align__(16) float  g_state [TOT1];
// split-K partial buffers
__device__ __align__(16) float  g_pq    [8  * TOT1];
__device__ __align__(16) float  g_pxg   [4  * TOT3];
__device__ __align__(16) float  g_phwr  [4  * TOT3];
__device__ __align__(16) float  g_prhwr [8  * TOT1];
__device__ __align__(16) float  g_pfc   [16 * TOTFC];

// ======================= PTX helpers =======================
__device__ __forceinline__ uint32_t smem_u32(const void* p) {
    uint32_t a;
    asm("{ .reg .u64 t; cvta.to.shared.u64 t, %1; cvt.u32.u64 %0, t; }" : "=r"(a) : "l"(p));
    return a;
}
#define CP_ASYNC16(dst, src) \
    asm volatile("cp.async.cg.shared.global [%0], [%1], 16;" :: "r"(dst), "l"(src))
#define CP_COMMIT() asm volatile("cp.async.commit_group;" ::: "memory")

__device__ __forceinline__ void ldsm_x4(uint32_t r[4], uint32_t addr) {
    asm volatile("ldmatrix.sync.aligned.m8n8.x4.shared.b16 {%0,%1,%2,%3}, [%4];"
                 : "=r"(r[0]), "=r"(r[1]), "=r"(r[2]), "=r"(r[3]) : "r"(addr));
}
// s8 x s8 -> s32, m16n8k32
__device__ __forceinline__ void mma_s8(int c[4], const uint32_t a[4],
                                       uint32_t b0, uint32_t b1) {
    asm volatile(
        "mma.sync.aligned.m16n8k32.row.col.s32.s8.s8.s32 "
        "{%0,%1,%2,%3}, {%4,%5,%6,%7}, {%8,%9}, {%0,%1,%2,%3};"
        : "+r"(c[0]), "+r"(c[1]), "+r"(c[2]), "+r"(c[3])
        : "r"(a[0]), "r"(a[1]), "r"(a[2]), "r"(a[3]), "r"(b0), "r"(b1));
}

// ======================= quantization kernels =======================
__global__ __launch_bounds__(256)
void quant_enc_kernel(const float* __restrict__ enc)
{
    const int warp = threadIdx.x >> 5, lane = threadIdx.x & 31;
    const size_t row = (size_t)blockIdx.x * 8 + warp;
    const float4* p4 = reinterpret_cast<const float4*>(enc + row * UNITS);

    float4 v[8];
    float mx = 0.f;
    #pragma unroll
    for (int i = 0; i < 8; i++) {
        v[i] = p4[lane + 32 * i];
        mx = fmaxf(mx, fmaxf(fmaxf(fabsf(v[i].x), fabsf(v[i].y)),
                             fmaxf(fabsf(v[i].z), fabsf(v[i].w))));
    }
    #pragma unroll
    for (int s = 16; s > 0; s >>= 1)
        mx = fmaxf(mx, __shfl_xor_sync(0xFFFFFFFF, mx, s));

    const float sinv = mx > 0.f ? 127.f / mx : 0.f;
    if (lane == 0) g_sA[row] = mx > 0.f ? mx / 127.f : 0.f;

    char4* q1 = reinterpret_cast<char4*>(g_enc_q1 + row * UNITS);
    char4* q0 = reinterpret_cast<char4*>(g_enc_q0 + row * UNITS);
    #pragma unroll
    for (int i = 0; i < 8; i++) {
        float a[4] = {v[i].x * sinv, v[i].y * sinv, v[i].z * sinv, v[i].w * sinv};
        char h[4], l[4];
        #pragma unroll
        for (int j = 0; j < 4; j++) {
            int hi = __float2int_rn(a[j]);
            int lo = __float2int_rn((a[j] - (float)hi) * 128.f);
            h[j] = (char)hi; l[j] = (char)lo;
        }
        q1[lane + 32 * i] = make_char4(h[0], h[1], h[2], h[3]);
        q0[lane + 32 * i] = make_char4(l[0], l[1], l[2], l[3]);
    }
}

__global__ __launch_bounds__(256)
void w1_colmax_kernel(const float* __restrict__ W1)
{
    __shared__ float smax[8][32];
    const int n0 = blockIdx.x * 32;
    const int nn = threadIdx.x & 31, kg = threadIdx.x >> 5;
    float mx = 0.f;
    for (int k = kg; k < UNITS; k += 8)
        mx = fmaxf(mx, fabsf(W1[(size_t)k * UNITS + n0 + nn]));
    smax[kg][nn] = mx;
    __syncthreads();
    if (threadIdx.x < 32) {
        float m = smax[0][nn];
        #pragma unroll
        for (int i = 1; i < 8; i++) m = fmaxf(m, smax[i][nn]);
        g_sB[n0 + nn]    = m > 0.f ? m / 127.f : 0.f;
        g_sBinv[n0 + nn] = m > 0.f ? 127.f / m : 0.f;
    }
}

__global__ __launch_bounds__(256)
void quant_w1_kernel(const float* __restrict__ W1)
{
    __shared__ float tile[32][33];
    const int n0 = blockIdx.x * 32, k0 = blockIdx.y * 32;
    const int tx = threadIdx.x, ty = threadIdx.y;
    #pragma unroll
    for (int i = 0; i < 4; i++)
        tile[ty + i * 8][tx] = W1[(size_t)(k0 + ty + i * 8) * UNITS + n0 + tx];
    __syncthreads();
    #pragma unroll
    for (int i = 0; i < 4; i++) {
        const int n = n0 + ty + i * 8;
        float v = tile[tx][ty + i * 8] * g_sBinv[n];
        int hi = __float2int_rn(v);
        int lo = __float2int_rn((v - (float)hi) * 128.f);
        size_t o = (size_t)n * UNITS + k0 + tx;
        g_w1t_q1[o] = (int8_t)hi;
        g_w1t_q0[o] = (int8_t)lo;
    }
}

// ======================= int8 warp-MMA score GEMM =======================
// CTA: (b, s-tile 128, n-tile 64), 256 threads, warp grid 4(m)x2(n),
// warp tile 32x32. K = 1024 int8 in 16 chunks of 64 (64B rows).
// Stage: A1 8K | A0 8K | B1 4K | B0 4K = 24KB, swizzle c ^= (row>>1)&3.
// 3 stages = 72KB -> 2 CTAs/SM. accm chain split into two ni-passes.
#define T_A1    0
#define T_A0    8192
#define T_B1    16384
#define T_B0    20480
#define STAGE_B 24576
#define NSTAGE  3
#define NCHUNK  16
#define SCORE_SMEM (NSTAGE * STAGE_B)     // 73728

__device__ __forceinline__ void fill_stage(uint32_t stage,
                                           const char* a1, const char* a0,
                                           const char* b1, const char* b0,
                                           int chunk, int tid)
{
    const int kb = chunk * 64;
    #pragma unroll
    for (int t = 0; t < 2; t++) {
        const int idx = t * 256 + tid;
        const int row = idx >> 2, c = idx & 3;
        const uint32_t so = (uint32_t)(row * 64 + ((c ^ ((row >> 1) & 3)) << 4));
        const size_t   go = (size_t)row * UNITS + kb + c * 16;
        CP_ASYNC16(stage + T_A1 + so, a1 + go);
        CP_ASYNC16(stage + T_A0 + so, a0 + go);
    }
    {
        const int row = tid >> 2, c = tid & 3;
        const uint32_t so = (uint32_t)(row * 64 + ((c ^ ((row >> 1) & 3)) << 4));
        const size_t   go = (size_t)row * UNITS + kb + c * 16;
        CP_ASYNC16(stage + T_B1 + so, b1 + go);
        CP_ASYNC16(stage + T_B0 + so, b0 + go);
    }
}

__global__ __launch_bounds__(256, 2)
void score_mma_kernel(const float* __restrict__ q,
                      const float* __restrict__ b1v,
                      const float* __restrict__ V)
{
    extern __shared__ __align__(128) char smem[];
    __shared__ float sacc[128];
    const uint32_t sb = smem_u32(smem);

    const int tid    = threadIdx.x;
    const int lane   = tid & 31;
    const int wid    = tid >> 5;
    const int warp_m = wid & 3;           // 0..3  (32 rows each)
    const int warp_n = wid >> 2;          // 0..1  (32 cols each)
    const int n0     = blockIdx.x * 64;
    const int s0     = blockIdx.y * 128;
    const int b      = blockIdx.z;

    if (tid < 128) sacc[tid] = 0.f;

    const char* a1p = (const char*)(g_enc_q1 + ((size_t)b * SEQ + s0) * UNITS);
    const char* a0p = (const char*)(g_enc_q0 + ((size_t)b * SEQ + s0) * UNITS);
    const char* b1p = (const char*)(g_w1t_q1 + (size_t)n0 * UNITS);
    const char* b0p = (const char*)(g_w1t_q0 + (size_t)n0 * UNITS);

    fill_stage(sb,           a1p, a0p, b1p, b0p, 0, tid); CP_COMMIT();
    fill_stage(sb + STAGE_B, a1p, a0p, b1p, b0p, 1, tid); CP_COMMIT();

    int acc1[2][4][4], accm[2][4][4];
    #pragma unroll
    for (int mi = 0; mi < 2; mi++)
        #pragma unroll
        for (int ni = 0; ni < 4; ni++)
            #pragma unroll
            for (int c = 0; c < 4; c++) { acc1[mi][ni][c] = 0; accm[mi][ni][c] = 0; }

    uint32_t a_off[2], xa[2], b_off[2], xb[2];
    #pragma unroll
    for (int mi = 0; mi < 2; mi++) {
        int row = warp_m * 32 + mi * 16 + (lane & 7) + ((lane >> 3) & 1) * 8;
        a_off[mi] = (uint32_t)row * 64;
        xa[mi]    = (uint32_t)((row >> 1) & 3);
    }
    #pragma unroll
    for (int p = 0; p < 2; p++) {
        int row = warp_n * 32 + p * 16 + (lane & 7) + ((lane >> 3) & 1) * 8;
        b_off[p] = (uint32_t)row * 64;
        xb[p]    = (uint32_t)((row >> 1) & 3);
    }
    const uint32_t ch = (uint32_t)(lane >> 4);   // k16-half selector

    #pragma unroll 1
    for (int c = 0; c < NCHUNK; c++) {
        if (c >= NCHUNK - 1) asm volatile("cp.async.wait_group 0;" ::: "memory");
        else                 asm volatile("cp.async.wait_group 1;" ::: "memory");
        __syncthreads();   // chunk c visible; iteration c-1 MMAs done everywhere

        const uint32_t slot = sb + (uint32_t)(c % NSTAGE) * STAGE_B;

        if (c + 2 < NCHUNK) {   // slot (c+2)%3 was consumed at iter c-1
            fill_stage(sb + (uint32_t)((c + 2) % NSTAGE) * STAGE_B,
                       a1p, a0p, b1p, b0p, c + 2, tid);
            CP_COMMIT();
        }

        #pragma unroll
        for (int j = 0; j < 2; j++) {     // two k32 steps per 64-chunk
            const uint32_t cj = (uint32_t)(j * 2) + ch;
            uint32_t bf1[2][4], bf0[2][4];
            #pragma unroll
            for (int p = 0; p < 2; p++) {
                uint32_t ad = slot + T_B1 + b_off[p] + ((cj ^ xb[p]) << 4);
                ldsm_x4(bf1[p], ad);
                ldsm_x4(bf0[p], ad + (T_B0 - T_B1));
            }
            #pragma unroll
            for (int mi = 0; mi < 2; mi++) {
                uint32_t ad = slot + T_A1 + a_off[mi] + ((cj ^ xa[mi]) << 4);
                uint32_t af1[4], af0[4];
                ldsm_x4(af1, ad);
                ldsm_x4(af0, ad + (T_A0 - T_A1));
                // pass 1: 8 independent MMAs (acc1 += A1*B1, accm += A1*B0)
                #pragma unroll
                for (int ni = 0; ni < 4; ni++) {
                    const int p = ni >> 1, h = ni & 1;
                    mma_s8(acc1[mi][ni], af1, bf1[p][h], bf1[p][h + 2]);
                    mma_s8(accm[mi][ni], af1, bf0[p][h], bf0[p][h + 2]);
                }
                // pass 2: accm += A0*B1 -- RAW producer is now >=4 issues back
                #pragma unroll
                for (int ni = 0; ni < 4; ni++) {
                    const int p = ni >> 1, h = ni & 1;
                    mma_s8(accm[mi][ni], af0, bf1[p][h], bf1[p][h + 2]);
                }
            }
        }
    }

    // Epilogue: val = sA*sB*(acc1 + accm/128); part[s] = sum_n V*tanh(val+q+b1)
    const size_t qb = (size_t)b * UNITS;
    const float* sArow = g_sA + (size_t)b * SEQ + s0;
    #pragma unroll
    for (int mi = 0; mi < 2; mi++) {
        float p0 = 0.f, p1 = 0.f;
        const int r   = warp_m * 32 + mi * 16 + (lane >> 2);
        const float sa0 = sArow[r], sa1 = sArow[r + 8];
        #pragma unroll
        for (int ni = 0; ni < 4; ni++) {
            #pragma unroll
            for (int cc = 0; cc < 4; cc++) {
                int n = n0 + warp_n * 32 + ni * 8 + (lane & 3) * 2 + (cc & 1);
                float sa  = (cc < 2) ? sa0 : sa1;
                float val = sa * g_sB[n] *
                            ((float)acc1[mi][ni][cc] + (float)accm[mi][ni][cc] * 0.0078125f);
                float t = V[n] * tanhf(val + q[qb + n] + b1v[n]);
                if (cc < 2) p0 += t; else p1 += t;
            }
        }
        p0 += __shfl_xor_sync(0xFFFFFFFF, p0, 1);
        p0 += __shfl_xor_sync(0xFFFFFFFF, p0, 2);
        p1 += __shfl_xor_sync(0xFFFFFFFF, p1, 1);
        p1 += __shfl_xor_sync(0xFFFFFFFF, p1, 2);
        if ((lane & 3) == 0) {
            atomicAdd(&sacc[r],     p0);
            atomicAdd(&sacc[r + 8], p1);
        }
    }
    __syncthreads();
    if (tid < 128)
        g_part[(size_t)blockIdx.x * (BATCH * SEQ) + (size_t)b * SEQ + s0 + tid] = sacc[tid];
}

// ======================= fp32 split-K SGEMM (R11, unchanged) =============
__device__ __forceinline__
void sgemm_part_body(const float* __restrict__ A, int lda,
                     const float* __restrict__ B, int ldb,
                     float* __restrict__ Cpart, int ldc,
                     int kbeg, int kend, int n0)
{
    __shared__ float As[16][128 + 4];
    __shared__ float Bs[16][64];

    const int tid = threadIdx.x;
    const int tm  = (tid >> 4) * 8;
    const int tn  = (tid & 15) * 4;

    float acc[8][4];
    #pragma unroll
    for (int i = 0; i < 8; i++)
        #pragma unroll
        for (int j = 0; j < 4; j++) acc[i][j] = 0.f;

    for (int kk = kbeg; kk < kend; kk += 16) {
        #pragma unroll
        for (int it = 0; it < 2; it++) {
            int t4 = it * 256 + tid;
            int row = t4 >> 2, col = (t4 & 3) * 4;
            float4 v = *reinterpret_cast<const float4*>(&A[(size_t)row * lda + kk + col]);
            As[col + 0][row] = v.x; As[col + 1][row] = v.y;
            As[col + 2][row] = v.z; As[col + 3][row] = v.w;
        }
        {
            int row = tid >> 4, c4 = (tid & 15) * 4;
            *reinterpret_cast<float4*>(&Bs[row][c4]) =
                *reinterpret_cast<const float4*>(&B[(size_t)(kk + row) * ldb + n0 + c4]);
        }
        __syncthreads();
        #pragma unroll
        for (int k = 0; k < 16; k++) {
            float ra[8], rb[4];
            *reinterpret_cast<float4*>(&ra[0]) = *reinterpret_cast<const float4*>(&As[k][tm]);
            *reinterpret_cast<float4*>(&ra[4]) = *reinterpret_cast<const float4*>(&As[k][tm + 4]);
            *reinterpret_cast<float4*>(&rb[0]) = *reinterpret_cast<const float4*>(&Bs[k][tn]);
            #pragma unroll
            for (int i = 0; i < 8; i++)
                #pragma unroll
                for (int j = 0; j < 4; j++)
                    acc[i][j] += ra[i] * rb[j];
        }
        __syncthreads();
    }
    #pragma unroll
    for (int j = 0; j < 4; j++)
        #pragma unroll
        for (int i = 0; i < 8; i++)
            Cpart[(size_t)(tm + i) * ldc + n0 + tn + j] = acc[i][j];
}

__global__ __launch_bounds__(256)
void sgemm_split_kernel(const float* __restrict__ A, int lda,
                        const float* __restrict__ B, int ldb,
                        float* __restrict__ part, int ldc,
                        int K, int S)
{
    const int s = blockIdx.y;
    const int steps = K / 16;
    const int per   = steps / S;
    sgemm_part_body(A, lda, B, ldb, part + (size_t)s * 128 * ldc, ldc,
                    s * per * 16, (s + 1) * per * 16, blockIdx.x * 64);
}

__global__ __launch_bounds__(256)
void sgemm_dual_split_kernel(const float* __restrict__ gin,
                             const float* __restrict__ hidden,
                             const float* __restrict__ Wk,
                             const float* __restrict__ Wr,
                             int S)
{
    const int s = blockIdx.y;
    if (blockIdx.z == 0) {
        const int steps = GINLEN / 16;
        const int per   = steps / S;
        sgemm_part_body(gin, GINLEN, Wk, G3U, g_pxg + (size_t)s * TOT3, G3U,
                        s * per * 16, (s + 1) * per * 16, blockIdx.x * 64);
    } else {
        const int steps = UNITS / 16;
        const int per   = steps / S;
        sgemm_part_body(hidden, UNITS, Wr, G3U, g_phwr + (size_t)s * TOT3, G3U,
                        s * per * 16, (s + 1) * per * 16, blockIdx.x * 64);
    }
}

__global__ __launch_bounds__(256)
void reduce_q_kernel(const float* __restrict__ b2)
{
    int i = blockIdx.x * 256 + threadIdx.x;
    float s = 0.f;
    #pragma unroll
    for (int t = 0; t < 8; t++) s += g_pq[(size_t)t * TOT1 + i];
    g_q[i] = s + b2[i & 1023];
}

__global__ __launch_bounds__(256)
void reduce_fc_kernel(const float* __restrict__ bfc, float* __restrict__ out_fc)
{
    int i = blockIdx.x * 256 + threadIdx.x;
    float s = 0.f;
    #pragma unroll
    for (int t = 0; t < 16; t++) s += g_pfc[(size_t)t * TOTFC + i];
    out_fc[i] = s + bfc[i & 63];
}

// ======================= remaining pipeline =======================
__global__ __launch_bounds__(256)
void softmax_kernel(const float* __restrict__ bV, float* __restrict__ out_attn)
{
    __shared__ float sh[SEQ];
    __shared__ float red[256];
    const int b = blockIdx.x, tid = threadIdx.x;
    const float bv = bV[0];

    float m = -1e30f;
    for (int i = tid; i < SEQ; i += 256) {
        size_t o = (size_t)b * SEQ + i;
        float s = bv;
        #pragma unroll
        for (int t = 0; t < NT2; t++)
            s += g_part[(size_t)t * (BATCH * SEQ) + o];
        sh[i] = s;
        m = fmaxf(m, s);
    }
    red[tid] = m; __syncthreads();
    for (int s = 128; s > 0; s >>= 1) {
        if (tid < s) red[tid] = fmaxf(red[tid], red[tid + s]);
        __syncthreads();
    }
    m = red[0]; __syncthreads();

    float sum = 0.f;
    for (int i = tid; i < SEQ; i += 256) {
        float e = expf(sh[i] - m);
        sh[i] = e;
        sum += e;
    }
    red[tid] = sum; __syncthreads();
    for (int s = 128; s > 0; s >>= 1) {
        if (tid < s) red[tid] += red[tid + s];
        __syncthreads();
    }
    float inv = 1.f / red[0];
    for (int i = tid; i < SEQ; i += 256)
        out_attn[(size_t)b * SEQ + i] = sh[i] * inv;
}

__global__ __launch_bounds__(256)
void context_kernel(const float* __restrict__ enc, const float* __restrict__ attn)
{
    __shared__ float w[SEQ];
    const int b = blockIdx.y, u0 = blockIdx.x * 256, tid = threadIdx.x;

    for (int i = tid; i < SEQ; i += 256)
        w[i] = attn[(size_t)b * SEQ + i];
    __syncthreads();

    const float* e = enc + (size_t)b * SEQ * UNITS + u0 + tid;
    float acc = 0.f;
    #pragma unroll 8
    for (int s = 0; s < SEQ; s++)
        acc += w[s] * e[(size_t)s * UNITS];
    g_gin[(size_t)b * GINLEN + u0 + tid] = acc;
}

__global__ void copyx_kernel(const float* __restrict__ x)
{
    int i = blockIdx.x * 256 + threadIdx.x;
    if (i < BATCH * INDIM) {
        int b = i >> 6, u = i & 63;
        g_gin[(size_t)b * GINLEN + UNITS + u] = x[i];
    }
}

__global__ __launch_bounds__(256)
void gates_kernel(const float* __restrict__ hidden, const float* __restrict__ bg)
{
    int i = blockIdx.x * 256 + threadIdx.x;
    int b = i >> 10, u = i & 1023;
    size_t oz = (size_t)b * G3U + u;
    size_t orr = oz + UNITS;
    float xz = bg[u], xr = bg[UNITS + u];
    #pragma unroll
    for (int t = 0; t < 4; t++) {
        xz += g_pxg[(size_t)t * TOT3 + oz] + g_phwr[(size_t)t * TOT3 + oz];
        xr += g_pxg[(size_t)t * TOT3 + orr] + g_phwr[(size_t)t * TOT3 + orr];
    }
    float z = 1.f / (1.f + expf(-xz));
    float r = 1.f / (1.f + expf(-xr));
    g_z[i]  = z;
    g_rh[i] = r * hidden[i];
}

__global__ __launch_bounds__(256)
void state_kernel(const float* __restrict__ hidden, const float* __restrict__ bg,
                  float* __restrict__ out_state)
{
    int i = blockIdx.x * 256 + threadIdx.x;
    int b = i >> 10, u = i & 1023;
    size_t oh = (size_t)b * G3U + 2 * UNITS + u;
    float xh = bg[2 * UNITS + u];
    #pragma unroll
    for (int t = 0; t < 4; t++) xh += g_pxg[(size_t)t * TOT3 + oh];
    float rw = 0.f;
    #pragma unroll
    for (int t = 0; t < 8; t++) rw += g_prhwr[(size_t)t * TOT1 + i];
    float hh = tanhf(xh + rw);
    float z  = g_z[i];
    float st = z * hidden[i] + (1.f - z) * hh;
    out_state[i] = st;
    g_state[i]   = st;
}

// ----------------------------------------------------------------------------
extern "C" void kernel_launch(void* const* d_in, const int* in_sizes, int n_in,
                              void* d_out_v, int out_size)
{
    const float* x      = (const float*)d_in[0];
    const float* hidden = (const float*)d_in[1];
    const float* enc    = (const float*)d_in[2];
    const float* W1     = (const float*)d_in[3];
    const float* b1     = (const float*)d_in[4];
    const float* W2     = (const float*)d_in[5];
    const float* b2     = (const float*)d_in[6];
    const float* V      = (const float*)d_in[7];
    const float* bV     = (const float*)d_in[8];
    const float* Wk     = (const float*)d_in[9];
    const float* Wr     = (const float*)d_in[10];
    const float* bg     = (const float*)d_in[11];
    const float* Wfc    = (const float*)d_in[12];
    const float* bfc    = (const float*)d_in[13];

    float* d_out     = (float*)d_out_v;
    float* out_fc    = d_out;
    float* out_state = d_out + BATCH * INDIM;
    float* out_attn  = d_out + BATCH * INDIM + BATCH * UNITS;

    float *q, *rh, *state, *pq, *prhwr, *pfc, *gin;
    cudaGetSymbolAddress((void**)&q,     g_q);
    cudaGetSymbolAddress((void**)&rh,    g_rh);
    cudaGetSymbolAddress((void**)&state, g_state);
    cudaGetSymbolAddress((void**)&pq,    g_pq);
    cudaGetSymbolAddress((void**)&prhwr, g_prhwr);
    cudaGetSymbolAddress((void**)&pfc,   g_pfc);
    cudaGetSymbolAddress((void**)&gin,   g_gin);

    cudaFuncSetAttribute(score_mma_kernel,
                         cudaFuncAttributeMaxDynamicSharedMemorySize, SCORE_SMEM);

    // 1. quantize operands
    quant_enc_kernel<<<(BATCH * SEQ) / 8, 256>>>(enc);
    w1_colmax_kernel<<<UNITS / 32, 256>>>(W1);
    quant_w1_kernel<<<dim3(32, 32), dim3(32, 8)>>>(W1);
    // 2. q = hidden @ W2 + b2 (split-K 8)
    sgemm_split_kernel<<<dim3(UNITS / 64, 8), 256>>>(hidden, UNITS, W2, UNITS, pq, UNITS, UNITS, 8);
    reduce_q_kernel<<<TOT1 / 256, 256>>>(b2);
    // 3. int8 tensor-core score GEMM (accm RAW chain de-serialized)
    score_mma_kernel<<<dim3(NT2, SEQ / 128, BATCH), 256, SCORE_SMEM>>>(q, b1, V);
    // 4. fused reduce + softmax (output slab 3)
    softmax_kernel<<<BATCH, 256>>>(bV, out_attn);
    // 5. gin = [context | x]
    copyx_kernel<<<(BATCH * INDIM + 255) / 256, 256>>>(x);
    context_kernel<<<dim3(UNITS / 256, BATCH), 256>>>(enc, out_attn);
    // 6. GRU projections split-K
    sgemm_dual_split_kernel<<<dim3(G3U / 64, 4, 2), 256>>>(gin, hidden, Wk, Wr, 4);
    // 7. gates (fused partial reduction)
    gates_kernel<<<TOT1 / 256, 256>>>(hidden, bg);
    // 8. (r*h) @ Wr_h split-K 8
    sgemm_split_kernel<<<dim3(UNITS / 64, 8), 256>>>(rh, UNITS, Wr + 2 * UNITS, G3U, prhwr, UNITS, UNITS, 8);
    // 9. state (fused partial reduction, output slab 2)
    state_kernel<<<TOT1 / 256, 256>>>(hidden, bg, out_state);
    // 10. out = state @ Wfc + bfc (split-K 16)
    sgemm_split_kernel<<<dim3(INDIM / 64, 16), 256>>>(state, UNITS, Wfc, INDIM, pfc, INDIM, UNITS, 16);
    reduce_fc_kernel<<<TOTFC / 256, 256>>>(bfc, out_fc);
}